// round 3
// baseline (speedup 1.0000x reference)
#include <cuda_runtime.h>
#include <math.h>

#define NN 9216
#define DD 1024
#define NB 72          // NN / 128 tile blocks per dim
#define NTILES 2628    // NB*(NB+1)/2 upper-triangular tiles

// -------- device-global accumulators / scratch (no allocations allowed) -----
__device__ float  g_sq[NN];
__device__ float  g_norm[NN];
__device__ float  g_agg_sum;
__device__ double g_sim_sum;

// ---------------------------------------------------------------------------
__global__ void init_kernel() {
    g_agg_sum = 0.0f;
    g_sim_sum = 0.0;
}

// one warp per row: squared norm + norm
__global__ void norms_kernel(const float* __restrict__ F) {
    int row = blockIdx.x * blockDim.y + threadIdx.y;
    if (row >= NN) return;
    int lane = threadIdx.x;
    const float4* Fr = reinterpret_cast<const float4*>(F + (size_t)row * DD);
    float s = 0.0f;
#pragma unroll
    for (int w = 0; w < 8; w++) {
        float4 v = Fr[lane + w * 32];
        s += v.x * v.x + v.y * v.y + v.z * v.z + v.w * v.w;
    }
#pragma unroll
    for (int o = 16; o > 0; o >>= 1) s += __shfl_down_sync(0xffffffffu, s, o);
    if (lane == 0) {
        g_sq[row] = s;
        g_norm[row] = sqrtf(s);
    }
}

// ---------------------------------------------------------------------------
// MLP: 8 rows per block, 128 threads.
//   h1 = relu(bn1(x @ W1 + b1)), h2 = relu(bn2(h1 @ W2 + b2)),
//   agg = sigmoid(h2 @ W3 + b3); atomicAdd into g_agg_sum.
__global__ __launch_bounds__(128) void mlp_kernel(
    const float* __restrict__ F, const float* __restrict__ scores,
    const float* __restrict__ W1, const float* __restrict__ b1,
    const float* __restrict__ g1, const float* __restrict__ be1,
    const float* __restrict__ W2, const float* __restrict__ b2,
    const float* __restrict__ g2, const float* __restrict__ be2,
    const float* __restrict__ W3, const float* __restrict__ b3)
{
    __shared__ float xs[8][1028];   // padded row stride (16B-aligned float4 reads)
    __shared__ float hs[8][128];
    __shared__ float h2s[8][64];

    const int tid = threadIdx.x;
    const int r0  = blockIdx.x * 8;

    // stage features + score into smem
    for (int idx = tid; idx < 8 * 1024; idx += 128) {
        int r = idx >> 10, k = idx & 1023;
        xs[r][k] = F[(size_t)(r0 + r) * DD + k];
    }
    if (tid < 8) xs[tid][1024] = scores[r0 + tid];
    __syncthreads();

    const float RSQ = rsqrtf(1.0f + 1e-5f);

    // layer 1: each thread owns one of 128 output features, all 8 rows
    {
        const int j = tid;
        float acc[8];
#pragma unroll
        for (int r = 0; r < 8; r++) acc[r] = 0.0f;
        for (int k = 0; k < 1024; k += 4) {
            float w0 = W1[(k + 0) * 128 + j];
            float w1 = W1[(k + 1) * 128 + j];
            float w2 = W1[(k + 2) * 128 + j];
            float w3 = W1[(k + 3) * 128 + j];
#pragma unroll
            for (int r = 0; r < 8; r++) {
                float4 x = *reinterpret_cast<const float4*>(&xs[r][k]);
                acc[r] = fmaf(x.x, w0, acc[r]);
                acc[r] = fmaf(x.y, w1, acc[r]);
                acc[r] = fmaf(x.z, w2, acc[r]);
                acc[r] = fmaf(x.w, w3, acc[r]);
            }
        }
        float wl = W1[1024 * 128 + j];
#pragma unroll
        for (int r = 0; r < 8; r++) acc[r] = fmaf(xs[r][1024], wl, acc[r]);

        const float G = g1[j] * RSQ, B = be1[j], bb = b1[j];
#pragma unroll
        for (int r = 0; r < 8; r++)
            hs[r][j] = fmaxf(fmaf(G, acc[r] + bb, B), 0.0f);
    }
    __syncthreads();

    // layer 2: threads 0..63
    if (tid < 64) {
        const int j = tid;
        float acc[8];
#pragma unroll
        for (int r = 0; r < 8; r++) acc[r] = 0.0f;
#pragma unroll 4
        for (int k = 0; k < 128; k++) {
            float w = W2[k * 64 + j];
#pragma unroll
            for (int r = 0; r < 8; r++) acc[r] = fmaf(hs[r][k], w, acc[r]);
        }
        const float G = g2[j] * RSQ, B = be2[j], bb = b2[j];
#pragma unroll
        for (int r = 0; r < 8; r++)
            h2s[r][j] = fmaxf(fmaf(G, acc[r] + bb, B), 0.0f);
    }
    __syncthreads();

    // layer 3 + sigmoid: threads 0..7, one per row
    if (tid < 8) {
        const int r = tid;
        float s = b3[0];
#pragma unroll 8
        for (int k = 0; k < 64; k++) s = fmaf(h2s[r][k], W3[k], s);
        float a = 1.0f / (1.0f + __expf(-s));
        atomicAdd(&g_agg_sum, a);
    }
}

// ---------------------------------------------------------------------------
// Gram tile + fused Gaussian-similarity epilogue + reduction.
// 128x128 output tile, BK=16, 256 threads, 8x8 micro-tiles.
// Only upper-triangular tiles (bi<=bj); off-diagonal tiles weighted x2.
__global__ __launch_bounds__(256) void gram_sim_kernel(const float* __restrict__ F) {
    __shared__ float As[16][128];
    __shared__ float Bs[16][128];
    __shared__ float warpsum[8];

    // linear tile id -> (bi, bj) with bi <= bj, t = bj*(bj+1)/2 + bi
    const int t = blockIdx.x;
    int bj = (int)((sqrtf(8.0f * (float)t + 1.0f) - 1.0f) * 0.5f);
    while ((bj + 1) * (bj + 2) / 2 <= t) bj++;
    while (bj * (bj + 1) / 2 > t) bj--;
    const int bi = t - bj * (bj + 1) / 2;

    const int tid = threadIdx.x;
    const int tx = tid & 15, ty = tid >> 4;
    const int rowA0 = bi * 128, rowB0 = bj * 128;

    float acc[8][8];
#pragma unroll
    for (int i = 0; i < 8; i++)
#pragma unroll
        for (int j = 0; j < 8; j++) acc[i][j] = 0.0f;

    for (int kt = 0; kt < DD / 16; kt++) {
        const int k0 = kt * 16;
        // cooperative load: 512 float4 per operand tile, 2 per thread
#pragma unroll
        for (int l = 0; l < 2; l++) {
            int gidx = tid + l * 256;
            int m = gidx >> 2;
            int k4 = (gidx & 3) * 4;
            float4 va = *reinterpret_cast<const float4*>(
                &F[(size_t)(rowA0 + m) * DD + k0 + k4]);
            As[k4 + 0][m] = va.x; As[k4 + 1][m] = va.y;
            As[k4 + 2][m] = va.z; As[k4 + 3][m] = va.w;
            float4 vb = *reinterpret_cast<const float4*>(
                &F[(size_t)(rowB0 + m) * DD + k0 + k4]);
            Bs[k4 + 0][m] = vb.x; Bs[k4 + 1][m] = vb.y;
            Bs[k4 + 2][m] = vb.z; Bs[k4 + 3][m] = vb.w;
        }
        __syncthreads();
#pragma unroll
        for (int k = 0; k < 16; k++) {
            float a[8], b[8];
            float4 a0 = *reinterpret_cast<const float4*>(&As[k][ty * 8]);
            float4 a1 = *reinterpret_cast<const float4*>(&As[k][ty * 8 + 4]);
            float4 b0 = *reinterpret_cast<const float4*>(&Bs[k][tx * 8]);
            float4 b1 = *reinterpret_cast<const float4*>(&Bs[k][tx * 8 + 4]);
            a[0] = a0.x; a[1] = a0.y; a[2] = a0.z; a[3] = a0.w;
            a[4] = a1.x; a[5] = a1.y; a[6] = a1.z; a[7] = a1.w;
            b[0] = b0.x; b[1] = b0.y; b[2] = b0.z; b[3] = b0.w;
            b[4] = b1.x; b[5] = b1.y; b[6] = b1.z; b[7] = b1.w;
#pragma unroll
            for (int i = 0; i < 8; i++)
#pragma unroll
                for (int j = 0; j < 8; j++)
                    acc[i][j] = fmaf(a[i], b[j], acc[i][j]);
        }
        __syncthreads();
    }

    // --- fused similarity epilogue ---
    const int i0 = rowA0 + ty * 8;
    const int j0 = rowB0 + tx * 8;
    float sqi[8], sqj[8], nri[8], nrj[8];
#pragma unroll
    for (int i = 0; i < 8; i++) { sqi[i] = g_sq[i0 + i]; nri[i] = g_norm[i0 + i]; }
#pragma unroll
    for (int j = 0; j < 8; j++) { sqj[j] = g_sq[j0 + j]; nrj[j] = g_norm[j0 + j]; }

    float lsum = 0.0f;
#pragma unroll
    for (int i = 0; i < 8; i++) {
#pragma unroll
        for (int j = 0; j < 8; j++) {
            const int gi = i0 + i, gj = j0 + j;
            float s;
            if (gi == gj) {
                s = 1.0f;
            } else {
                const float g = acc[i][j];
                const float np   = fmaxf(nri[i] * nrj[j], 1e-6f);
                const float cosv = g / np;
                const float d2   = fmaxf(sqi[i] + sqj[j] - 2.0f * g, 0.0f);
                const float den  = fmaxf(1024.0f * (1.0f + cosv), 1e-6f);
                s = __expf(-d2 / den);
            }
            lsum += s;
        }
    }

    // block reduce
#pragma unroll
    for (int o = 16; o > 0; o >>= 1) lsum += __shfl_down_sync(0xffffffffu, lsum, o);
    if ((tid & 31) == 0) warpsum[tid >> 5] = lsum;
    __syncthreads();
    if (tid == 0) {
        float tot = 0.0f;
#pragma unroll
        for (int w = 0; w < 8; w++) tot += warpsum[w];
        const double wgt = (bi == bj) ? 1.0 : 2.0;
        atomicAdd(&g_sim_sum, wgt * (double)tot);
    }
}

// ---------------------------------------------------------------------------
__global__ void finalize_kernel(float* __restrict__ out) {
    const double ma = (double)g_agg_sum / (double)NN;
    const double ms = g_sim_sum / ((double)NN * (double)NN);
    out[0] = (float)(ma * ms);
}

// ---------------------------------------------------------------------------
extern "C" void kernel_launch(void* const* d_in, const int* in_sizes, int n_in,
                              void* d_out, int out_size)
{
    const float* F      = (const float*)d_in[0];   // [9216, 1024]
    const float* scores = (const float*)d_in[1];   // [9216]
    const float* W1     = (const float*)d_in[2];   // [1025, 128]
    const float* b1     = (const float*)d_in[3];
    const float* g1     = (const float*)d_in[4];
    const float* be1    = (const float*)d_in[5];
    const float* W2     = (const float*)d_in[6];   // [128, 64]
    const float* b2     = (const float*)d_in[7];
    const float* g2     = (const float*)d_in[8];
    const float* be2    = (const float*)d_in[9];
    const float* W3     = (const float*)d_in[10];  // [64, 1]
    const float* b3     = (const float*)d_in[11];

    init_kernel<<<1, 1>>>();
    norms_kernel<<<NN / 8, dim3(32, 8)>>>(F);
    mlp_kernel<<<NN / 8, 128>>>(F, scores, W1, b1, g1, be1, W2, b2, g2, be2, W3, b3);
    gram_sim_kernel<<<NTILES, 256>>>(F);
    finalize_kernel<<<1, 1>>>((float*)d_out);
}

// round 4
// speedup vs baseline: 1.0000x; 1.0000x over previous
#include <cuda_runtime.h>
#include <math.h>

#define NN 9216
#define DD 1024
#define NB 72          // NN / 128 tile blocks per dim
#define NTILES 2628    // NB*(NB+1)/2 upper-triangular tiles

// -------- device-global accumulators / scratch (no allocations allowed) -----
__device__ float  g_sq[NN];
__device__ float  g_norm[NN];
__device__ float  g_agg_sum;
__device__ double g_sim_sum;

// ---------------------------------------------------------------------------
__global__ void init_kernel() {
    g_agg_sum = 0.0f;
    g_sim_sum = 0.0;
}

// one warp per row: squared norm + norm
__global__ void norms_kernel(const float* __restrict__ F) {
    int row = blockIdx.x * blockDim.y + threadIdx.y;
    if (row >= NN) return;
    int lane = threadIdx.x;
    const float4* Fr = reinterpret_cast<const float4*>(F + (size_t)row * DD);
    float s = 0.0f;
#pragma unroll
    for (int w = 0; w < 8; w++) {
        float4 v = Fr[lane + w * 32];
        s += v.x * v.x + v.y * v.y + v.z * v.z + v.w * v.w;
    }
#pragma unroll
    for (int o = 16; o > 0; o >>= 1) s += __shfl_down_sync(0xffffffffu, s, o);
    if (lane == 0) {
        g_sq[row] = s;
        g_norm[row] = sqrtf(s);
    }
}

// ---------------------------------------------------------------------------
// MLP: 8 rows per block, 128 threads.
//   h1 = relu(bn1(x @ W1 + b1)), h2 = relu(bn2(h1 @ W2 + b2)),
//   agg = sigmoid(h2 @ W3 + b3); atomicAdd into g_agg_sum.
__global__ __launch_bounds__(128) void mlp_kernel(
    const float* __restrict__ F, const float* __restrict__ scores,
    const float* __restrict__ W1, const float* __restrict__ b1,
    const float* __restrict__ g1, const float* __restrict__ be1,
    const float* __restrict__ W2, const float* __restrict__ b2,
    const float* __restrict__ g2, const float* __restrict__ be2,
    const float* __restrict__ W3, const float* __restrict__ b3)
{
    __shared__ float xs[8][1028];   // padded row stride (16B-aligned float4 reads)
    __shared__ float hs[8][128];
    __shared__ float h2s[8][64];

    const int tid = threadIdx.x;
    const int r0  = blockIdx.x * 8;

    // stage features + score into smem
    for (int idx = tid; idx < 8 * 1024; idx += 128) {
        int r = idx >> 10, k = idx & 1023;
        xs[r][k] = F[(size_t)(r0 + r) * DD + k];
    }
    if (tid < 8) xs[tid][1024] = scores[r0 + tid];
    __syncthreads();

    const float RSQ = rsqrtf(1.0f + 1e-5f);

    // layer 1: each thread owns one of 128 output features, all 8 rows
    {
        const int j = tid;
        float acc[8];
#pragma unroll
        for (int r = 0; r < 8; r++) acc[r] = 0.0f;
        for (int k = 0; k < 1024; k += 4) {
            float w0 = W1[(k + 0) * 128 + j];
            float w1 = W1[(k + 1) * 128 + j];
            float w2 = W1[(k + 2) * 128 + j];
            float w3 = W1[(k + 3) * 128 + j];
#pragma unroll
            for (int r = 0; r < 8; r++) {
                float4 x = *reinterpret_cast<const float4*>(&xs[r][k]);
                acc[r] = fmaf(x.x, w0, acc[r]);
                acc[r] = fmaf(x.y, w1, acc[r]);
                acc[r] = fmaf(x.z, w2, acc[r]);
                acc[r] = fmaf(x.w, w3, acc[r]);
            }
        }
        float wl = W1[1024 * 128 + j];
#pragma unroll
        for (int r = 0; r < 8; r++) acc[r] = fmaf(xs[r][1024], wl, acc[r]);

        const float G = g1[j] * RSQ, B = be1[j], bb = b1[j];
#pragma unroll
        for (int r = 0; r < 8; r++)
            hs[r][j] = fmaxf(fmaf(G, acc[r] + bb, B), 0.0f);
    }
    __syncthreads();

    // layer 2: threads 0..63
    if (tid < 64) {
        const int j = tid;
        float acc[8];
#pragma unroll
        for (int r = 0; r < 8; r++) acc[r] = 0.0f;
#pragma unroll 4
        for (int k = 0; k < 128; k++) {
            float w = W2[k * 64 + j];
#pragma unroll
            for (int r = 0; r < 8; r++) acc[r] = fmaf(hs[r][k], w, acc[r]);
        }
        const float G = g2[j] * RSQ, B = be2[j], bb = b2[j];
#pragma unroll
        for (int r = 0; r < 8; r++)
            h2s[r][j] = fmaxf(fmaf(G, acc[r] + bb, B), 0.0f);
    }
    __syncthreads();

    // layer 3 + sigmoid: threads 0..7, one per row
    if (tid < 8) {
        const int r = tid;
        float s = b3[0];
#pragma unroll 8
        for (int k = 0; k < 64; k++) s = fmaf(h2s[r][k], W3[k], s);
        float a = 1.0f / (1.0f + __expf(-s));
        atomicAdd(&g_agg_sum, a);
    }
}

// ---------------------------------------------------------------------------
// Gram tile + fused Gaussian-similarity epilogue + reduction.
// 128x128 output tile, BK=16, 256 threads, 8x8 micro-tiles.
// Only upper-triangular tiles (bi<=bj); off-diagonal tiles weighted x2.
__global__ __launch_bounds__(256) void gram_sim_kernel(const float* __restrict__ F) {
    __shared__ float As[16][128];
    __shared__ float Bs[16][128];
    __shared__ float warpsum[8];

    // linear tile id -> (bi, bj) with bi <= bj, t = bj*(bj+1)/2 + bi
    const int t = blockIdx.x;
    int bj = (int)((sqrtf(8.0f * (float)t + 1.0f) - 1.0f) * 0.5f);
    while ((bj + 1) * (bj + 2) / 2 <= t) bj++;
    while (bj * (bj + 1) / 2 > t) bj--;
    const int bi = t - bj * (bj + 1) / 2;

    const int tid = threadIdx.x;
    const int tx = tid & 15, ty = tid >> 4;
    const int rowA0 = bi * 128, rowB0 = bj * 128;

    float acc[8][8];
#pragma unroll
    for (int i = 0; i < 8; i++)
#pragma unroll
        for (int j = 0; j < 8; j++) acc[i][j] = 0.0f;

    for (int kt = 0; kt < DD / 16; kt++) {
        const int k0 = kt * 16;
        // cooperative load: 512 float4 per operand tile, 2 per thread
#pragma unroll
        for (int l = 0; l < 2; l++) {
            int gidx = tid + l * 256;
            int m = gidx >> 2;
            int k4 = (gidx & 3) * 4;
            float4 va = *reinterpret_cast<const float4*>(
                &F[(size_t)(rowA0 + m) * DD + k0 + k4]);
            As[k4 + 0][m] = va.x; As[k4 + 1][m] = va.y;
            As[k4 + 2][m] = va.z; As[k4 + 3][m] = va.w;
            float4 vb = *reinterpret_cast<const float4*>(
                &F[(size_t)(rowB0 + m) * DD + k0 + k4]);
            Bs[k4 + 0][m] = vb.x; Bs[k4 + 1][m] = vb.y;
            Bs[k4 + 2][m] = vb.z; Bs[k4 + 3][m] = vb.w;
        }
        __syncthreads();
#pragma unroll
        for (int k = 0; k < 16; k++) {
            float a[8], b[8];
            float4 a0 = *reinterpret_cast<const float4*>(&As[k][ty * 8]);
            float4 a1 = *reinterpret_cast<const float4*>(&As[k][ty * 8 + 4]);
            float4 b0 = *reinterpret_cast<const float4*>(&Bs[k][tx * 8]);
            float4 b1 = *reinterpret_cast<const float4*>(&Bs[k][tx * 8 + 4]);
            a[0] = a0.x; a[1] = a0.y; a[2] = a0.z; a[3] = a0.w;
            a[4] = a1.x; a[5] = a1.y; a[6] = a1.z; a[7] = a1.w;
            b[0] = b0.x; b[1] = b0.y; b[2] = b0.z; b[3] = b0.w;
            b[4] = b1.x; b[5] = b1.y; b[6] = b1.z; b[7] = b1.w;
#pragma unroll
            for (int i = 0; i < 8; i++)
#pragma unroll
                for (int j = 0; j < 8; j++)
                    acc[i][j] = fmaf(a[i], b[j], acc[i][j]);
        }
        __syncthreads();
    }

    // --- fused similarity epilogue ---
    const int i0 = rowA0 + ty * 8;
    const int j0 = rowB0 + tx * 8;
    float sqi[8], sqj[8], nri[8], nrj[8];
#pragma unroll
    for (int i = 0; i < 8; i++) { sqi[i] = g_sq[i0 + i]; nri[i] = g_norm[i0 + i]; }
#pragma unroll
    for (int j = 0; j < 8; j++) { sqj[j] = g_sq[j0 + j]; nrj[j] = g_norm[j0 + j]; }

    float lsum = 0.0f;
#pragma unroll
    for (int i = 0; i < 8; i++) {
#pragma unroll
        for (int j = 0; j < 8; j++) {
            const int gi = i0 + i, gj = j0 + j;
            float s;
            if (gi == gj) {
                s = 1.0f;
            } else {
                const float g = acc[i][j];
                const float np   = fmaxf(nri[i] * nrj[j], 1e-6f);
                const float cosv = g / np;
                const float d2   = fmaxf(sqi[i] + sqj[j] - 2.0f * g, 0.0f);
                const float den  = fmaxf(1024.0f * (1.0f + cosv), 1e-6f);
                s = __expf(-d2 / den);
            }
            lsum += s;
        }
    }

    // block reduce
#pragma unroll
    for (int o = 16; o > 0; o >>= 1) lsum += __shfl_down_sync(0xffffffffu, lsum, o);
    if ((tid & 31) == 0) warpsum[tid >> 5] = lsum;
    __syncthreads();
    if (tid == 0) {
        float tot = 0.0f;
#pragma unroll
        for (int w = 0; w < 8; w++) tot += warpsum[w];
        const double wgt = (bi == bj) ? 1.0 : 2.0;
        atomicAdd(&g_sim_sum, wgt * (double)tot);
    }
}

// ---------------------------------------------------------------------------
__global__ void finalize_kernel(float* __restrict__ out) {
    const double ma = (double)g_agg_sum / (double)NN;
    const double ms = g_sim_sum / ((double)NN * (double)NN);
    out[0] = (float)(ma * ms);
}

// ---------------------------------------------------------------------------
extern "C" void kernel_launch(void* const* d_in, const int* in_sizes, int n_in,
                              void* d_out, int out_size)
{
    const float* F      = (const float*)d_in[0];   // [9216, 1024]
    const float* scores = (const float*)d_in[1];   // [9216]
    const float* W1     = (const float*)d_in[2];   // [1025, 128]
    const float* b1     = (const float*)d_in[3];
    const float* g1     = (const float*)d_in[4];
    const float* be1    = (const float*)d_in[5];
    const float* W2     = (const float*)d_in[6];   // [128, 64]
    const float* b2     = (const float*)d_in[7];
    const float* g2     = (const float*)d_in[8];
    const float* be2    = (const float*)d_in[9];
    const float* W3     = (const float*)d_in[10];  // [64, 1]
    const float* b3     = (const float*)d_in[11];

    init_kernel<<<1, 1>>>();
    norms_kernel<<<NN / 8, dim3(32, 8)>>>(F);
    mlp_kernel<<<NN / 8, 128>>>(F, scores, W1, b1, g1, be1, W2, b2, g2, be2, W3, b3);
    gram_sim_kernel<<<NTILES, 256>>>(F);
    finalize_kernel<<<1, 1>>>((float*)d_out);
}